// round 6
// baseline (speedup 1.0000x reference)
#include <cuda_runtime.h>
#include <math.h>

// ---------------------------------------------------------------------------
// MLP 2 -> 64 -> 64 -> 64 -> 1 with chaotic activation
//   act(z) = g(g(cos(z)*0.5 + 0.5)),  g(x) = R*x*(1-x),  R = 3.82843
// 2 points per thread. Weights in shared memory (broadcast LDS.128 of
// pre-packed f32x2 pairs). Hidden activations register-resident during each
// layer; inter-layer handoff through per-thread columns of a single in-place
// shared buffer (reads fully hoisted before writes -> no hazard, no syncs).
// Inner products use packed fma.rn.f32x2 (SASS FFMA2): 2x fp32 throughput.
// cos() is a custom branch-free Cody-Waite + Taylor pair (args are bounded),
// avoiding the libm CALL and any --use_fast_math dependence.
// ---------------------------------------------------------------------------

#define R_CONST 3.82843f

typedef unsigned long long u64;

__device__ __forceinline__ u64 f2fma(u64 a, u64 b, u64 c) {
    u64 d; asm("fma.rn.f32x2 %0, %1, %2, %3;" : "=l"(d) : "l"(a), "l"(b), "l"(c)); return d;
}
__device__ __forceinline__ u64 f2mul(u64 a, u64 b) {
    u64 d; asm("mul.rn.f32x2 %0, %1, %2;" : "=l"(d) : "l"(a), "l"(b)); return d;
}
__device__ __forceinline__ u64 f2add(u64 a, u64 b) {
    u64 d; asm("add.rn.f32x2 %0, %1, %2;" : "=l"(d) : "l"(a), "l"(b)); return d;
}
__device__ __forceinline__ u64 pk2(float lo, float hi) {
    u64 r; asm("mov.b64 %0, {%1, %2};" : "=l"(r) : "f"(lo), "f"(hi)); return r;
}
__device__ __forceinline__ void upk2(u64 v, float& lo, float& hi) {
    asm("mov.b64 {%0, %1}, %2;" : "=f"(lo), "=f"(hi) : "l"(v));
}

// Accurate cos for |z| < ~1e5 (pre-activations here are |z| <~ 10).
// Cody-Waite 2-constant reduction + degree-9 sin / degree-8 cos Taylor.
// Max abs error ~1e-7. Branch-free (SEL), no libcalls.
__device__ __forceinline__ float cos_fast(float z) {
    const float TWO_OVER_PI = 0.636619772367581343f;
    const float MAGIC = 12582912.0f;                  // 1.5 * 2^23
    float big = fmaf(z, TWO_OVER_PI, MAGIC);
    int   qi  = __float_as_int(big);                  // low bits = round(z*2/pi)
    float n   = big - MAGIC;
    // r = z - n*pi/2 (split constant)
    float r = fmaf(n, -1.57079601287841796875f, z);   // pio2_hi (24-bit safe)
    r = fmaf(n, -3.139164786504813e-7f, r);           // pio2_mid
    r = fmaf(n, -5.390302529957765e-15f, r);          // pio2_lo
    float r2 = r * r;
    // sin(r) = r*(1 + r2*(-1/6 + r2*(1/120 + r2*(-1/5040 + r2/362880))))
    float ps = fmaf(r2, 2.75573137e-6f, -1.98412698e-4f);
    ps = fmaf(r2, ps, 8.33333333e-3f);
    ps = fmaf(r2, ps, -1.66666667e-1f);
    float sinr = r * fmaf(r2, ps, 1.0f);
    // cos(r) = 1 + r2*(-1/2 + r2*(1/24 + r2*(-1/720 + r2/40320)))
    float pc = fmaf(r2, 2.48015873e-5f, -1.38888889e-3f);
    pc = fmaf(r2, pc, 4.16666667e-2f);
    pc = fmaf(r2, pc, -0.5f);
    float cosr = fmaf(r2, pc, 1.0f);
    // quadrant: cos(r + q*pi/2): q=0:+cos 1:-sin 2:-cos 3:+sin
    int q = qi & 3;
    float v = (q & 1) ? sinr : cosr;
    return ((q == 1) | (q == 2)) ? -v : v;
}

// Scalar activation (final layer)
__device__ __forceinline__ float act1(float z) {
    float x = fmaf(cos_fast(z), 0.5f, 0.5f);
    float t = R_CONST * x; x = t * (1.0f - x);
    t = R_CONST * x;       x = t * (1.0f - x);
    return x;
}

// Packed activation for a pair of pre-activations
__device__ __forceinline__ u64 act2(float z0, float z1) {
    float c0 = fmaf(cos_fast(z0), 0.5f, 0.5f);
    float c1 = fmaf(cos_fast(z1), 0.5f, 0.5f);
    u64 x = pk2(c0, c1);
    const u64 Rp  = pk2(R_CONST, R_CONST);
    const u64 one = pk2(1.0f, 1.0f);
    const u64 m1  = pk2(-1.0f, -1.0f);
    u64 t  = f2mul(Rp, x);
    u64 om = f2fma(x, m1, one);   // 1 - x
    x = f2mul(t, om);
    t  = f2mul(Rp, x);
    om = f2fma(x, m1, one);
    x = f2mul(t, om);
    return x;
}

// ---------------------------------------------------------------------------

constexpr int TPB = 128;
constexpr int PPT = 2;                 // points per thread
constexpr int PPB = TPB * PPT;         // 256 points per block

// Shared-memory layout (float indices)
constexpr int SM_W2 = 0;               // 64x64
constexpr int SM_W3 = 4096;            // 64x64
constexpr int SM_W1 = 8192;            // 64x2
constexpr int SM_W4 = 8320;            // 1x64
constexpr int SM_B1 = 8384;
constexpr int SM_B2 = 8448;
constexpr int SM_B3 = 8512;
constexpr int SM_B4 = 8576;            // 1
constexpr int SM_HB = 8592;            // byte offset 34368 (16B aligned)
// h buffers: PPT * 32 pairs * TPB columns of u64
constexpr size_t SMEM_BYTES = (size_t)SM_HB * 4 + (size_t)PPT * 32 * TPB * 8; // 99904 B

// One 64->64 hidden layer for 2 points, in place (reads hoisted to regs).
__device__ __forceinline__ void hidden_layer2(const float* __restrict__ sm,
                                              int wOff, int bOff,
                                              u64* __restrict__ hbA,
                                              u64* __restrict__ hbB, int tid) {
    u64 hA[32], hB[32];
#pragma unroll
    for (int p = 0; p < 32; p++) {
        hA[p] = hbA[p * TPB + tid];
        hB[p] = hbB[p * TPB + tid];
    }
    const float* W = sm + wOff;
    for (int j = 0; j < 64; j += 2) {
        const ulonglong2* w0 = (const ulonglong2*)(W + j * 64);
        const ulonglong2* w1 = (const ulonglong2*)(W + (j + 1) * 64);
        u64 aA0 = 0ull, aA1 = 0ull, aA2 = 0ull, aA3 = 0ull;
        u64 aB0 = 0ull, aB1 = 0ull, aB2 = 0ull, aB3 = 0ull;
#pragma unroll
        for (int q = 0; q < 16; q++) {
            ulonglong2 wa = w0[q];              // broadcast LDS.128
            ulonglong2 wb = w1[q];
            aA0 = f2fma(wa.x, hA[2 * q],     aA0);
            aA1 = f2fma(wa.y, hA[2 * q + 1], aA1);
            aA2 = f2fma(wb.x, hA[2 * q],     aA2);
            aA3 = f2fma(wb.y, hA[2 * q + 1], aA3);
            aB0 = f2fma(wa.x, hB[2 * q],     aB0);
            aB1 = f2fma(wa.y, hB[2 * q + 1], aB1);
            aB2 = f2fma(wb.x, hB[2 * q],     aB2);
            aB3 = f2fma(wb.y, hB[2 * q + 1], aB3);
        }
        float b0 = sm[bOff + j], b1 = sm[bOff + j + 1];
        float l, h;
        u64 s;
        s = f2add(aA0, aA1); upk2(s, l, h); float zA0 = (l + h) + b0;
        s = f2add(aA2, aA3); upk2(s, l, h); float zA1 = (l + h) + b1;
        s = f2add(aB0, aB1); upk2(s, l, h); float zB0 = (l + h) + b0;
        s = f2add(aB2, aB3); upk2(s, l, h); float zB1 = (l + h) + b1;
        hbA[(j >> 1) * TPB + tid] = act2(zA0, zA1);
        hbB[(j >> 1) * TPB + tid] = act2(zB0, zB1);
    }
}

__global__ void __launch_bounds__(TPB)
mlp_kernel(const float* __restrict__ X,
           const float* __restrict__ W1, const float* __restrict__ B1,
           const float* __restrict__ W2, const float* __restrict__ B2,
           const float* __restrict__ W3, const float* __restrict__ B3,
           const float* __restrict__ W4, const float* __restrict__ B4,
           float* __restrict__ O, int N) {
    extern __shared__ float sm[];
    const int tid = threadIdx.x;

    // Cooperative weight staging (vectorized)
    {
        const float4* s4 = (const float4*)W2;
        float4*       t4 = (float4*)(sm + SM_W2);
        for (int i = tid; i < 1024; i += TPB) t4[i] = s4[i];
        s4 = (const float4*)W3;
        t4 = (float4*)(sm + SM_W3);
        for (int i = tid; i < 1024; i += TPB) t4[i] = s4[i];
    }
    if (tid < 128) sm[SM_W1 + tid] = W1[tid];
    if (tid < 64) {
        sm[SM_W4 + tid] = W4[tid];
        sm[SM_B1 + tid] = B1[tid];
        sm[SM_B2 + tid] = B2[tid];
        sm[SM_B3 + tid] = B3[tid];
    }
    if (tid == 0) sm[SM_B4] = B4[0];
    __syncthreads();

    u64* hbA = (u64*)(sm + SM_HB);          // point A: 32*TPB u64
    u64* hbB = hbA + 32 * TPB;              // point B: 32*TPB u64

    const int base = blockIdx.x * PPB;
    const int gidA = base + tid;
    const int gidB = base + TPB + tid;
    float xA0 = 0.0f, xA1 = 0.0f, xB0 = 0.0f, xB1 = 0.0f;
    if (gidA < N) { float2 v = ((const float2*)X)[gidA]; xA0 = v.x; xA1 = v.y; }
    if (gidB < N) { float2 v = ((const float2*)X)[gidB]; xB0 = v.x; xB1 = v.y; }

    // Layer 1: 2 -> 64 (both points)
#pragma unroll 4
    for (int j = 0; j < 64; j += 2) {
        float w00 = sm[SM_W1 + 2 * j],     w01 = sm[SM_W1 + 2 * j + 1];
        float w10 = sm[SM_W1 + 2 * j + 2], w11 = sm[SM_W1 + 2 * j + 3];
        float b0 = sm[SM_B1 + j], b1 = sm[SM_B1 + j + 1];
        float zA0 = fmaf(w00, xA0, fmaf(w01, xA1, b0));
        float zA1 = fmaf(w10, xA0, fmaf(w11, xA1, b1));
        float zB0 = fmaf(w00, xB0, fmaf(w01, xB1, b0));
        float zB1 = fmaf(w10, xB0, fmaf(w11, xB1, b1));
        hbA[(j >> 1) * TPB + tid] = act2(zA0, zA1);
        hbB[(j >> 1) * TPB + tid] = act2(zB0, zB1);
    }

    // Layers 2 & 3: 64 -> 64, in place (per-thread columns, no syncs needed)
    hidden_layer2(sm, SM_W2, SM_B2, hbA, hbB, tid);
    hidden_layer2(sm, SM_W3, SM_B3, hbA, hbB, tid);

    // Layer 4: 64 -> 1 (both points)
    {
        u64 hA[32], hB[32];
#pragma unroll
        for (int p = 0; p < 32; p++) {
            hA[p] = hbA[p * TPB + tid];
            hB[p] = hbB[p * TPB + tid];
        }
        const ulonglong2* w = (const ulonglong2*)(sm + SM_W4);
        u64 aA0 = 0ull, aA1 = 0ull, aB0 = 0ull, aB1 = 0ull;
#pragma unroll
        for (int q = 0; q < 16; q++) {
            ulonglong2 wv = w[q];
            aA0 = f2fma(wv.x, hA[2 * q],     aA0);
            aA1 = f2fma(wv.y, hA[2 * q + 1], aA1);
            aB0 = f2fma(wv.x, hB[2 * q],     aB0);
            aB1 = f2fma(wv.y, hB[2 * q + 1], aB1);
        }
        float b4 = sm[SM_B4];
        float l, h;
        u64 s;
        s = f2add(aA0, aA1); upk2(s, l, h); float zA = (l + h) + b4;
        s = f2add(aB0, aB1); upk2(s, l, h); float zB = (l + h) + b4;
        if (gidA < N) O[gidA] = act1(zA);
        if (gidB < N) O[gidB] = act1(zB);
    }
}

// ---------------------------------------------------------------------------

extern "C" void kernel_launch(void* const* d_in, const int* in_sizes, int n_in,
                              void* d_out, int out_size) {
    const float* X  = (const float*)d_in[0];
    const float* W1 = (const float*)d_in[1];
    const float* B1 = (const float*)d_in[2];
    const float* W2 = (const float*)d_in[3];
    const float* B2 = (const float*)d_in[4];
    const float* W3 = (const float*)d_in[5];
    const float* B3 = (const float*)d_in[6];
    const float* W4 = (const float*)d_in[7];
    const float* B4 = (const float*)d_in[8];
    float* O = (float*)d_out;

    const int N = in_sizes[0] / 2;

    // Opt-in to >48KB dynamic shared memory (host-side, idempotent, capture-safe)
    (void)cudaFuncSetAttribute(mlp_kernel,
                               cudaFuncAttributeMaxDynamicSharedMemorySize,
                               (int)SMEM_BYTES);

    const int blocks = (N + PPB - 1) / PPB;
    mlp_kernel<<<blocks, TPB, SMEM_BYTES>>>(X, W1, B1, W2, B2, W3, B3, W4, B4, O, N);
}

// round 8
// speedup vs baseline: 1.2156x; 1.2156x over previous
#include <cuda_runtime.h>
#include <math.h>

// ---------------------------------------------------------------------------
// MLP 2 -> 64 -> 64 -> 64 -> 1 with chaotic activation.
//   Reference act: x = cos(z)*0.5+0.5; x = R x (1-x) twice.
//   Algebraic identity: x(1-x) = (1-cos^2 z)/4 = sin^2(z)/4, so
//     act(z) = v*(R^2/4 - (R^3/16)*v),   v = sin^2(z)   (pi-periodic).
//   v is computed via packed mod-pi range reduction + MUFU.SIN (off the FMA
//   pipe), making the activation ~3.5 FMA-pipe ops/value instead of ~22.
// 2 points per thread; weights in smem (broadcast LDS.128 of packed f32x2
// pairs); h-activations register-resident per layer, handed off through
// per-thread smem columns (conflict-free, no syncs). Inner products use
// fma.rn.f32x2 (SASS FFMA2) for 2x fp32 throughput.
// ---------------------------------------------------------------------------

#define R_D 3.82843

typedef unsigned long long u64;

__device__ __forceinline__ u64 f2fma(u64 a, u64 b, u64 c) {
    u64 d; asm("fma.rn.f32x2 %0, %1, %2, %3;" : "=l"(d) : "l"(a), "l"(b), "l"(c)); return d;
}
__device__ __forceinline__ u64 f2mul(u64 a, u64 b) {
    u64 d; asm("mul.rn.f32x2 %0, %1, %2;" : "=l"(d) : "l"(a), "l"(b)); return d;
}
__device__ __forceinline__ u64 f2add(u64 a, u64 b) {
    u64 d; asm("add.rn.f32x2 %0, %1, %2;" : "=l"(d) : "l"(a), "l"(b)); return d;
}
__device__ __forceinline__ u64 pk2(float lo, float hi) {
    u64 r; asm("mov.b64 %0, {%1, %2};" : "=l"(r) : "f"(lo), "f"(hi)); return r;
}
__device__ __forceinline__ void upk2(u64 v, float& lo, float& hi) {
    asm("mov.b64 {%0, %1}, %2;" : "=f"(lo), "=f"(hi) : "l"(v));
}

// Activation coefficients (double-evaluated, rounded once to f32)
#define ACT_C0 ((float)(R_D * R_D / 4.0))            //  R^2/4
#define ACT_C1 ((float)(-(R_D * R_D * R_D) / 16.0))  // -R^3/16
// mod-pi reduction constants
#define INV_PI   0.3183098861837907f
#define RMAGIC   12582912.0f                         // 1.5 * 2^23
#define PI_HI    3.14159202575683593750f             // 24-bit-safe split of pi
#define PI_MID   6.278329573009626e-7f

// Scalar activation (final layer)
__device__ __forceinline__ float act1(float z) {
    float big = fmaf(z, INV_PI, RMAGIC);
    float n   = big - RMAGIC;                        // round(z/pi)
    float r   = fmaf(n, -PI_HI, z);
    r = fmaf(n, -PI_MID, r);
    float s = __sinf(r);                             // MUFU.SIN, |r| <= pi/2
    float v = s * s;                                 // sin^2(z)
    return v * fmaf(v, ACT_C1, ACT_C0);
}

// Packed activation for a pair of pre-activations
__device__ __forceinline__ u64 act2(float z0, float z1) {
    u64 z   = pk2(z0, z1);
    u64 big = f2fma(z, pk2(INV_PI, INV_PI), pk2(RMAGIC, RMAGIC));
    u64 n   = f2add(big, pk2(-RMAGIC, -RMAGIC));
    u64 r   = f2fma(n, pk2(-PI_HI, -PI_HI), z);
    r = f2fma(n, pk2(-PI_MID, -PI_MID), r);
    float r0, r1; upk2(r, r0, r1);
    float s0 = __sinf(r0);
    float s1 = __sinf(r1);
    u64 s = pk2(s0, s1);
    u64 v = f2mul(s, s);
    return f2mul(v, f2fma(v, pk2(ACT_C1, ACT_C1), pk2(ACT_C0, ACT_C0)));
}

// ---------------------------------------------------------------------------

constexpr int TPB = 128;
constexpr int PPT = 2;                 // points per thread
constexpr int PPB = TPB * PPT;         // 256 points per block

// Shared-memory layout (float indices)
constexpr int SM_W2 = 0;               // 64x64
constexpr int SM_W3 = 4096;            // 64x64
constexpr int SM_W1 = 8192;            // 64x2
constexpr int SM_W4 = 8320;            // 1x64
constexpr int SM_B1 = 8384;
constexpr int SM_B2 = 8448;
constexpr int SM_B3 = 8512;
constexpr int SM_B4 = 8576;            // 1
constexpr int SM_HB = 8592;            // byte offset 34368 (16B aligned)
constexpr size_t SMEM_BYTES = (size_t)SM_HB * 4 + (size_t)PPT * 32 * TPB * 8; // 99904 B

// One 64->64 hidden layer for 2 points, in place (reads hoisted to regs).
__device__ __forceinline__ void hidden_layer2(const float* __restrict__ sm,
                                              int wOff, int bOff,
                                              u64* __restrict__ hbA,
                                              u64* __restrict__ hbB, int tid) {
    u64 hA[32], hB[32];
#pragma unroll
    for (int p = 0; p < 32; p++) {
        hA[p] = hbA[p * TPB + tid];
        hB[p] = hbB[p * TPB + tid];
    }
    const float* W = sm + wOff;
#pragma unroll 2
    for (int j = 0; j < 64; j += 2) {
        const ulonglong2* w0 = (const ulonglong2*)(W + j * 64);
        const ulonglong2* w1 = (const ulonglong2*)(W + (j + 1) * 64);
        float b0 = sm[bOff + j], b1 = sm[bOff + j + 1];
        // bias folded into one accumulator lane of each chain
        u64 aA0 = pk2(b0, 0.0f), aA1 = 0ull, aA2 = pk2(b1, 0.0f), aA3 = 0ull;
        u64 aB0 = pk2(b0, 0.0f), aB1 = 0ull, aB2 = pk2(b1, 0.0f), aB3 = 0ull;
#pragma unroll
        for (int q = 0; q < 16; q++) {
            ulonglong2 wa = w0[q];              // broadcast LDS.128
            ulonglong2 wb = w1[q];
            aA0 = f2fma(wa.x, hA[2 * q],     aA0);
            aA1 = f2fma(wa.y, hA[2 * q + 1], aA1);
            aA2 = f2fma(wb.x, hA[2 * q],     aA2);
            aA3 = f2fma(wb.y, hA[2 * q + 1], aA3);
            aB0 = f2fma(wa.x, hB[2 * q],     aB0);
            aB1 = f2fma(wa.y, hB[2 * q + 1], aB1);
            aB2 = f2fma(wb.x, hB[2 * q],     aB2);
            aB3 = f2fma(wb.y, hB[2 * q + 1], aB3);
        }
        float l, h;
        u64 s;
        s = f2add(aA0, aA1); upk2(s, l, h); float zA0 = l + h;
        s = f2add(aA2, aA3); upk2(s, l, h); float zA1 = l + h;
        s = f2add(aB0, aB1); upk2(s, l, h); float zB0 = l + h;
        s = f2add(aB2, aB3); upk2(s, l, h); float zB1 = l + h;
        hbA[(j >> 1) * TPB + tid] = act2(zA0, zA1);
        hbB[(j >> 1) * TPB + tid] = act2(zB0, zB1);
    }
}

__global__ void __launch_bounds__(TPB)
mlp_kernel(const float* __restrict__ X,
           const float* __restrict__ W1, const float* __restrict__ B1,
           const float* __restrict__ W2, const float* __restrict__ B2,
           const float* __restrict__ W3, const float* __restrict__ B3,
           const float* __restrict__ W4, const float* __restrict__ B4,
           float* __restrict__ O, int N) {
    extern __shared__ float sm[];
    const int tid = threadIdx.x;

    // Cooperative weight staging (vectorized)
    {
        const float4* s4 = (const float4*)W2;
        float4*       t4 = (float4*)(sm + SM_W2);
        for (int i = tid; i < 1024; i += TPB) t4[i] = s4[i];
        s4 = (const float4*)W3;
        t4 = (float4*)(sm + SM_W3);
        for (int i = tid; i < 1024; i += TPB) t4[i] = s4[i];
    }
    if (tid < 128) sm[SM_W1 + tid] = W1[tid];
    if (tid < 64) {
        sm[SM_W4 + tid] = W4[tid];
        sm[SM_B1 + tid] = B1[tid];
        sm[SM_B2 + tid] = B2[tid];
        sm[SM_B3 + tid] = B3[tid];
    }
    if (tid == 0) sm[SM_B4] = B4[0];
    __syncthreads();

    u64* hbA = (u64*)(sm + SM_HB);          // point A: 32*TPB u64
    u64* hbB = hbA + 32 * TPB;              // point B: 32*TPB u64

    const int base = blockIdx.x * PPB;
    const int gidA = base + tid;
    const int gidB = base + TPB + tid;
    float xA0 = 0.0f, xA1 = 0.0f, xB0 = 0.0f, xB1 = 0.0f;
    if (gidA < N) { float2 v = ((const float2*)X)[gidA]; xA0 = v.x; xA1 = v.y; }
    if (gidB < N) { float2 v = ((const float2*)X)[gidB]; xB0 = v.x; xB1 = v.y; }

    // Layer 1: 2 -> 64 (both points)
#pragma unroll 4
    for (int j = 0; j < 64; j += 2) {
        float w00 = sm[SM_W1 + 2 * j],     w01 = sm[SM_W1 + 2 * j + 1];
        float w10 = sm[SM_W1 + 2 * j + 2], w11 = sm[SM_W1 + 2 * j + 3];
        float b0 = sm[SM_B1 + j], b1 = sm[SM_B1 + j + 1];
        float zA0 = fmaf(w00, xA0, fmaf(w01, xA1, b0));
        float zA1 = fmaf(w10, xA0, fmaf(w11, xA1, b1));
        float zB0 = fmaf(w00, xB0, fmaf(w01, xB1, b0));
        float zB1 = fmaf(w10, xB0, fmaf(w11, xB1, b1));
        hbA[(j >> 1) * TPB + tid] = act2(zA0, zA1);
        hbB[(j >> 1) * TPB + tid] = act2(zB0, zB1);
    }

    // Layers 2 & 3: 64 -> 64, in place (per-thread columns, no syncs needed)
    hidden_layer2(sm, SM_W2, SM_B2, hbA, hbB, tid);
    hidden_layer2(sm, SM_W3, SM_B3, hbA, hbB, tid);

    // Layer 4: 64 -> 1 (both points)
    {
        u64 hA[32], hB[32];
#pragma unroll
        for (int p = 0; p < 32; p++) {
            hA[p] = hbA[p * TPB + tid];
            hB[p] = hbB[p * TPB + tid];
        }
        const ulonglong2* w = (const ulonglong2*)(sm + SM_W4);
        float b4 = sm[SM_B4];
        u64 aA0 = pk2(b4, 0.0f), aA1 = 0ull;
        u64 aB0 = pk2(b4, 0.0f), aB1 = 0ull;
#pragma unroll
        for (int q = 0; q < 16; q++) {
            ulonglong2 wv = w[q];
            aA0 = f2fma(wv.x, hA[2 * q],     aA0);
            aA1 = f2fma(wv.y, hA[2 * q + 1], aA1);
            aB0 = f2fma(wv.x, hB[2 * q],     aB0);
            aB1 = f2fma(wv.y, hB[2 * q + 1], aB1);
        }
        float l, h;
        u64 s;
        s = f2add(aA0, aA1); upk2(s, l, h); float zA = l + h;
        s = f2add(aB0, aB1); upk2(s, l, h); float zB = l + h;
        if (gidA < N) O[gidA] = act1(zA);
        if (gidB < N) O[gidB] = act1(zB);
    }
}

// ---------------------------------------------------------------------------

extern "C" void kernel_launch(void* const* d_in, const int* in_sizes, int n_in,
                              void* d_out, int out_size) {
    const float* X  = (const float*)d_in[0];
    const float* W1 = (const float*)d_in[1];
    const float* B1 = (const float*)d_in[2];
    const float* W2 = (const float*)d_in[3];
    const float* B2 = (const float*)d_in[4];
    const float* W3 = (const float*)d_in[5];
    const float* B3 = (const float*)d_in[6];
    const float* W4 = (const float*)d_in[7];
    const float* B4 = (const float*)d_in[8];
    float* O = (float*)d_out;

    const int N = in_sizes[0] / 2;

    // Opt-in to >48KB dynamic shared memory (host-side, idempotent, capture-safe)
    (void)cudaFuncSetAttribute(mlp_kernel,
                               cudaFuncAttributeMaxDynamicSharedMemorySize,
                               (int)SMEM_BYTES);

    const int blocks = (N + PPB - 1) / PPB;
    mlp_kernel<<<blocks, TPB, SMEM_BYTES>>>(X, W1, B1, W2, B2, W3, B3, W4, B4, O, N);
}